// round 10
// baseline (speedup 1.0000x reference)
#include <cuda_runtime.h>
#include <math.h>
#include <stdint.h>
#include <stddef.h>

#define BB   32
#define TT   4096
#define TP   1024
#define DD   64
#define HH   512
#define G4   2048
#define OUTD 6
#define NCTA 128

// ---------------- scratch ----------------
static __device__ float d_sig[BB * TT];
static __device__ float d_c1 [BB * 64 * 2048];
static __device__ float d_c2 [BB * 64 * 1024];
static __device__ float d_ze [BB * TP * DD];
static __device__ float d_z  [BB * TP * DD];
static __device__ float d_xg [(size_t)BB * TP * G4];
static __device__ float d_h0 [(size_t)BB * TP * HH];
static __device__ float d_h1s[(size_t)BB * TP * HH];
static __device__ float d_hbuf[2 * HH * BB];
static __device__ int   d_flags[TP];

// ---------------- tokenizer ----------------
__global__ void k_mean(const float* __restrict__ x) {
    int idx = blockIdx.x * 256 + threadIdx.x;            // b*T + t
    const float4* xp = (const float4*)x + (size_t)idx * 16;
    float s = 0.f;
#pragma unroll
    for (int i = 0; i < 16; i++) { float4 v = xp[i]; s += v.x + v.y + v.z + v.w; }
    d_sig[idx] = s * (1.0f / 64.0f);
}

__global__ void k_conv1(const float* __restrict__ w1, const float* __restrict__ b1) {
    __shared__ float ws[256];
    __shared__ float bs[64];
    int tid = threadIdx.x;
    if (tid < 256) ws[tid] = w1[tid];
    if (tid < 64)  bs[tid] = b1[tid];
    __syncthreads();
    int b = blockIdx.y;
    int p = blockIdx.x * 256 + tid;                      // 0..2047
    const float* sg = d_sig + (size_t)b * TT;
    float in[4];
#pragma unroll
    for (int j = 0; j < 4; j++) {
        int q = 2 * p + j - 1;
        in[j] = (q >= 0 && q < TT) ? sg[q] : 0.f;
    }
    for (int o = 0; o < 64; o++) {
        float a = bs[o];
#pragma unroll
        for (int j = 0; j < 4; j++) a = fmaf(ws[o * 4 + j], in[j], a);
        d_c1[((size_t)(b * 64 + o)) * 2048 + p] = fmaxf(a, 0.f);
    }
}

__global__ void k_conv2(const float* __restrict__ w2, const float* __restrict__ b2) {
    extern __shared__ float sm2[];
    float* ws    = sm2;                 // 64*64*4
    float* patch = ws + 16384;          // 64*67
    float* bs    = patch + 64 * 67;
    int tid = threadIdx.x;
    for (int i = tid; i < 16384; i += 256) ws[i] = w2[i];
    if (tid < 64) bs[tid] = b2[tid];
    int b  = blockIdx.y;
    int p0 = blockIdx.x * 32;
    int q0 = 2 * p0 - 1;
    for (int i = tid; i < 64 * 67; i += 256) {
        int c = i / 67, dq = i % 67, q = q0 + dq;
        patch[i] = (q >= 0 && q < 2048) ? d_c1[((size_t)(b * 64 + c)) * 2048 + q] : 0.f;
    }
    __syncthreads();
    int po = tid & 31, og = tid >> 5;
    float acc[8];
#pragma unroll
    for (int i = 0; i < 8; i++) acc[i] = 0.f;
    for (int c = 0; c < 64; c++) {
        const float* pc = patch + c * 67 + 2 * po;
        float i0 = pc[0], i1 = pc[1], i2 = pc[2], i3 = pc[3];
#pragma unroll
        for (int oi = 0; oi < 8; oi++) {
            const float* wp = &ws[((og * 8 + oi) * 64 + c) * 4];
            acc[oi] = fmaf(wp[0], i0, fmaf(wp[1], i1, fmaf(wp[2], i2, fmaf(wp[3], i3, acc[oi]))));
        }
    }
#pragma unroll
    for (int oi = 0; oi < 8; oi++) {
        int o = og * 8 + oi;
        d_c2[((size_t)(b * 64 + o)) * 1024 + p0 + po] = fmaxf(acc[oi] + bs[o], 0.f);
    }
}

__global__ void k_conv3(const float* __restrict__ w3, const float* __restrict__ b3) {
    extern __shared__ float sm3[];
    float* ws    = sm3;                 // 64*64*3
    float* patch = ws + 12288;          // 64*34
    float* bs    = patch + 64 * 34;
    int tid = threadIdx.x;
    for (int i = tid; i < 12288; i += 256) ws[i] = w3[i];
    if (tid < 64) bs[tid] = b3[tid];
    int b  = blockIdx.y;
    int p0 = blockIdx.x * 32;
    int q0 = p0 - 1;
    for (int i = tid; i < 64 * 34; i += 256) {
        int c = i / 34, dq = i % 34, q = q0 + dq;
        patch[i] = (q >= 0 && q < 1024) ? d_c2[((size_t)(b * 64 + c)) * 1024 + q] : 0.f;
    }
    __syncthreads();
    int po = tid & 31, og = tid >> 5;
    float acc[8];
#pragma unroll
    for (int i = 0; i < 8; i++) acc[i] = 0.f;
    for (int c = 0; c < 64; c++) {
        const float* pc = patch + c * 34 + po;
        float i0 = pc[0], i1 = pc[1], i2 = pc[2];
#pragma unroll
        for (int oi = 0; oi < 8; oi++) {
            const float* wp = &ws[((og * 8 + oi) * 64 + c) * 3];
            acc[oi] = fmaf(wp[0], i0, fmaf(wp[1], i1, fmaf(wp[2], i2, acc[oi])));
        }
    }
#pragma unroll
    for (int oi = 0; oi < 8; oi++) {
        int d = og * 8 + oi;
        d_ze[((size_t)(b * TP) + p0 + po) * 64 + d] = acc[oi] + bs[d];
    }
}

__global__ void k_quant(const float* __restrict__ cb) {
    extern __shared__ float smq[];
    float* cbs = smq;            // 256*64
    float* cn  = smq + 16384;    // 256
    int tid = threadIdx.x;       // 128 threads
    for (int i = tid; i < 16384; i += 128) cbs[i] = cb[i];
    __syncthreads();
    for (int c = tid; c < 256; c += 128) {
        float s = 0.f;
        const float* cp = cbs + c * 64;
#pragma unroll
        for (int d = 0; d < 64; d++) s = fmaf(cp[d], cp[d], s);
        cn[c] = s;
    }
    __syncthreads();
    int g = blockIdx.x * 128 + tid;      // b*T' + p
    float4 zr[16];
    const float4* zp = (const float4*)d_ze + (size_t)g * 16;
    float szz = 0.f;
#pragma unroll
    for (int i = 0; i < 16; i++) {
        zr[i] = zp[i];
        szz += zr[i].x * zr[i].x + zr[i].y * zr[i].y + zr[i].z * zr[i].z + zr[i].w * zr[i].w;
    }
    float best = 3.0e38f; int bi = 0;
    for (int c = 0; c < 256; c++) {
        const float4* cp = (const float4*)cbs + c * 16;
        float dot = 0.f;
#pragma unroll
        for (int i = 0; i < 16; i++) {
            float4 w = cp[i];
            dot = fmaf(w.x, zr[i].x, fmaf(w.y, zr[i].y, fmaf(w.z, zr[i].z, fmaf(w.w, zr[i].w, dot))));
        }
        float dist = szz - 2.f * dot + cn[c];
        if (dist < best) { best = dist; bi = c; }
    }
    float4* zo = (float4*)d_z + (size_t)g * 16;
    const float4* cbest = (const float4*)cbs + bi * 16;
#pragma unroll
    for (int i = 0; i < 16; i++) zo[i] = cbest[i];
}

// ---------------- GEMM: C[M,N] = A[M,K]*B[N,K]^T + bias[N] ----------------
__global__ void __launch_bounds__(256) k_gemm(
    const float* __restrict__ A, const float* __restrict__ B,
    const float* __restrict__ bias, float* __restrict__ C,
    int M, int N, int K)
{
    __shared__ float As[16][68];
    __shared__ float Bs[16][68];
    int tid = threadIdx.x;
    int bm = blockIdx.y << 6, bn = blockIdx.x << 6;
    int lrow = tid >> 2;
    int lk   = (tid & 3) << 2;
    const float* Ag = A + (size_t)(bm + lrow) * K + lk;
    const float* Bg = B + (size_t)(bn + lrow) * K + lk;
    int tx = tid & 15, ty = tid >> 4;
    float acc[4][4];
#pragma unroll
    for (int i = 0; i < 4; i++)
#pragma unroll
        for (int j = 0; j < 4; j++) acc[i][j] = 0.f;

    for (int k0 = 0; k0 < K; k0 += 16) {
        float4 av = *(const float4*)(Ag + k0);
        float4 bv = *(const float4*)(Bg + k0);
        As[lk + 0][lrow] = av.x; As[lk + 1][lrow] = av.y;
        As[lk + 2][lrow] = av.z; As[lk + 3][lrow] = av.w;
        Bs[lk + 0][lrow] = bv.x; Bs[lk + 1][lrow] = bv.y;
        Bs[lk + 2][lrow] = bv.z; Bs[lk + 3][lrow] = bv.w;
        __syncthreads();
#pragma unroll
        for (int kk = 0; kk < 16; kk++) {
            float4 a4 = *(const float4*)(&As[kk][ty << 2]);
            float4 b4 = *(const float4*)(&Bs[kk][tx << 2]);
            acc[0][0] = fmaf(a4.x, b4.x, acc[0][0]); acc[0][1] = fmaf(a4.x, b4.y, acc[0][1]);
            acc[0][2] = fmaf(a4.x, b4.z, acc[0][2]); acc[0][3] = fmaf(a4.x, b4.w, acc[0][3]);
            acc[1][0] = fmaf(a4.y, b4.x, acc[1][0]); acc[1][1] = fmaf(a4.y, b4.y, acc[1][1]);
            acc[1][2] = fmaf(a4.y, b4.z, acc[1][2]); acc[1][3] = fmaf(a4.y, b4.w, acc[1][3]);
            acc[2][0] = fmaf(a4.z, b4.x, acc[2][0]); acc[2][1] = fmaf(a4.z, b4.y, acc[2][1]);
            acc[2][2] = fmaf(a4.z, b4.z, acc[2][2]); acc[2][3] = fmaf(a4.z, b4.w, acc[2][3]);
            acc[3][0] = fmaf(a4.w, b4.x, acc[3][0]); acc[3][1] = fmaf(a4.w, b4.y, acc[3][1]);
            acc[3][2] = fmaf(a4.w, b4.z, acc[3][2]); acc[3][3] = fmaf(a4.w, b4.w, acc[3][3]);
        }
        __syncthreads();
    }
    float bx = bias[bn + (tx << 2) + 0];
    float by = bias[bn + (tx << 2) + 1];
    float bz = bias[bn + (tx << 2) + 2];
    float bw = bias[bn + (tx << 2) + 3];
#pragma unroll
    for (int i = 0; i < 4; i++) {
        int row = bm + (ty << 2) + i;
        float4 o;
        o.x = acc[i][0] + bx; o.y = acc[i][1] + by;
        o.z = acc[i][2] + bz; o.w = acc[i][3] + bw;
        *(float4*)(C + (size_t)row * N + bn + (tx << 2)) = o;
    }
}

// ---------------- persistent LSTM ----------------
__global__ void k_lstm_init() {
    int i = blockIdx.x * 256 + threadIdx.x;
    if (i < TP) d_flags[i] = 0;
    if (i < HH * BB) d_hbuf[i] = 0.f;
}

__global__ void __launch_bounds__(256, 1) k_lstm(
    const float* __restrict__ xg,   // [B,T',4H]
    const float* __restrict__ whh,  // [4H,H]
    float* __restrict__ hseq)       // [B,T',H]
{
    extern __shared__ float sm[];
    float* whh_s = sm;                // 16*512
    float* hT    = sm + 16 * HH;      // 512*33
    float* gbuf  = hT + HH * 33;      // 2*16*32
    const int tid   = threadIdx.x;
    const int cta   = blockIdx.x;
    const int jbase = cta * 4;

    for (int m = 0; m < 16; m++) {
        int r = (m >> 2) * HH + jbase + (m & 3);
        const float* src = whh + (size_t)r * HH;
        for (int k = tid; k < HH; k += 256) whh_s[m * HH + k] = src[k];
    }
    const int lane  = tid & 31, wid = tid >> 5;
    const int mgrp  = (wid & 3) * 4;
    const int kh    = wid >> 2;
    const int kbase = kh * 256;
    const int ub    = tid >> 2, uu = tid & 3;
    float cst = 0.f;

    for (int t = 0; t < TP; t++) {
        const float4* hg = (const float4*)(d_hbuf + (size_t)(t & 1) * (HH * BB));
        for (int i = tid; i < HH * BB / 4; i += 256) {
            float4 v = hg[i];
            int k = i >> 3; int b4 = (i & 7) << 2;
            float* dst = hT + k * 33 + b4;
            dst[0] = v.x; dst[1] = v.y; dst[2] = v.z; dst[3] = v.w;
        }
        __syncthreads();
        {
            const float* wp0 = whh_s + (mgrp + 0) * HH + kbase;
            const float* wp1 = whh_s + (mgrp + 1) * HH + kbase;
            const float* wp2 = whh_s + (mgrp + 2) * HH + kbase;
            const float* wp3 = whh_s + (mgrp + 3) * HH + kbase;
            const float* hp  = hT + kbase * 33 + lane;
            float a0 = 0.f, a1 = 0.f, a2 = 0.f, a3 = 0.f;
#pragma unroll 8
            for (int kk = 0; kk < 256; kk += 4) {
                float4 w0 = *(const float4*)(wp0 + kk);
                float4 w1 = *(const float4*)(wp1 + kk);
                float4 w2 = *(const float4*)(wp2 + kk);
                float4 w3 = *(const float4*)(wp3 + kk);
                const float* hk = hp + kk * 33;
                float h0v = hk[0], h1v = hk[33], h2v = hk[66], h3v = hk[99];
                a0 = fmaf(w0.x, h0v, fmaf(w0.y, h1v, fmaf(w0.z, h2v, fmaf(w0.w, h3v, a0))));
                a1 = fmaf(w1.x, h0v, fmaf(w1.y, h1v, fmaf(w1.z, h2v, fmaf(w1.w, h3v, a1))));
                a2 = fmaf(w2.x, h0v, fmaf(w2.y, h1v, fmaf(w2.z, h2v, fmaf(w2.w, h3v, a2))));
                a3 = fmaf(w3.x, h0v, fmaf(w3.y, h1v, fmaf(w3.z, h2v, fmaf(w3.w, h3v, a3))));
            }
            gbuf[(kh * 16 + mgrp + 0) * 32 + lane] = a0;
            gbuf[(kh * 16 + mgrp + 1) * 32 + lane] = a1;
            gbuf[(kh * 16 + mgrp + 2) * 32 + lane] = a2;
            gbuf[(kh * 16 + mgrp + 3) * 32 + lane] = a3;
        }
        __syncthreads();
        if (tid < 128) {
            const int b = ub, u = uu;
            const int j = jbase + u;
            const float* xp = xg + ((size_t)b * TP + t) * G4 + j;
            float gi = gbuf[(0 + u) * 32 + b]  + gbuf[(16 + 0 + u) * 32 + b]  + xp[0];
            float gf = gbuf[(4 + u) * 32 + b]  + gbuf[(16 + 4 + u) * 32 + b]  + xp[512];
            float gg = gbuf[(8 + u) * 32 + b]  + gbuf[(16 + 8 + u) * 32 + b]  + xp[1024];
            float go = gbuf[(12 + u) * 32 + b] + gbuf[(16 + 12 + u) * 32 + b] + xp[1536];
            float iv = 1.f / (1.f + expf(-gi));
            float fv = 1.f / (1.f + expf(-gf));
            float gv = tanhf(gg);
            float ov = 1.f / (1.f + expf(-go));
            cst = fmaf(fv, cst, iv * gv);
            float hv = ov * tanhf(cst);
            d_hbuf[(size_t)((t + 1) & 1) * (HH * BB) + j * 32 + b] = hv;
            hseq[((size_t)b * TP + t) * HH + j] = hv;
        }
        if (t < TP - 1) {
            __threadfence();
            __syncthreads();
            if (tid == 0) {
                atomicAdd(&d_flags[t], 1);
                while (((volatile int*)d_flags)[t] < NCTA) { }
                __threadfence();
            }
            __syncthreads();
        }
    }
}

// ---------------- head ----------------
__global__ void k_head(const float* __restrict__ wout, const float* __restrict__ bout,
                       const float* __restrict__ hs, float* __restrict__ out)
{
    __shared__ float ws[OUTD * HH];
    __shared__ float bs[OUTD];
    int tid = threadIdx.x;
    for (int i = tid; i < OUTD * HH; i += 256) ws[i] = wout[i];
    if (tid < OUTD) bs[tid] = bout[tid];
    __syncthreads();
    int warp = tid >> 5, lane = tid & 31;
    int g = blockIdx.x * 8 + warp;       // b*T' + t
    const float4* hp = (const float4*)(hs + (size_t)g * HH);
    float4 hv[4];
#pragma unroll
    for (int c = 0; c < 4; c++) hv[c] = hp[lane + 32 * c];
#pragma unroll
    for (int o = 0; o < OUTD; o++) {
        const float4* wp = (const float4*)(ws + o * HH);
        float s = 0.f;
#pragma unroll
        for (int c = 0; c < 4; c++) {
            float4 w = wp[lane + 32 * c];
            s = fmaf(w.x, hv[c].x, fmaf(w.y, hv[c].y, fmaf(w.z, hv[c].z, fmaf(w.w, hv[c].w, s))));
        }
#pragma unroll
        for (int off = 16; off; off >>= 1) s += __shfl_xor_sync(0xFFFFFFFFu, s, off);
        if (lane == 0) out[(size_t)g * OUTD + o] = s + bs[o];
    }
}

// ---------------- launch ----------------
extern "C" void kernel_launch(void* const* d_in, const int* in_sizes, int n_in,
                              void* d_out, int out_size) {
    (void)in_sizes; (void)n_in; (void)out_size;
    const float* x     = (const float*)d_in[0];
    const float* cw1   = (const float*)d_in[1];
    const float* cb1   = (const float*)d_in[2];
    const float* cw2   = (const float*)d_in[3];
    const float* cb2   = (const float*)d_in[4];
    const float* cw3   = (const float*)d_in[5];
    const float* cb3   = (const float*)d_in[6];
    const float* cbook = (const float*)d_in[7];
    const float* wih0  = (const float*)d_in[8];
    const float* whh0  = (const float*)d_in[9];
    const float* bl0   = (const float*)d_in[10];
    const float* wih1  = (const float*)d_in[11];
    const float* whh1  = (const float*)d_in[12];
    const float* bl1   = (const float*)d_in[13];
    const float* wout  = (const float*)d_in[14];
    const float* bout  = (const float*)d_in[15];
    float* out = (float*)d_out;

    static float *pz = nullptr, *pxg = nullptr, *ph0 = nullptr, *ph1s = nullptr;
    if (!pz) {
        cudaGetSymbolAddress((void**)&pz,   d_z);
        cudaGetSymbolAddress((void**)&pxg,  d_xg);
        cudaGetSymbolAddress((void**)&ph0,  d_h0);
        cudaGetSymbolAddress((void**)&ph1s, d_h1s);
        const int smem_conv2 = (16384 + 64 * 67 + 64) * 4;
        const int smem_conv3 = (12288 + 64 * 34 + 64) * 4;
        const int smem_quant = (16384 + 256) * 4;
        const int smem_lstm  = (16 * HH + HH * 33 + 2 * 16 * 32) * 4;
        cudaFuncSetAttribute(k_conv2, cudaFuncAttributeMaxDynamicSharedMemorySize, smem_conv2);
        cudaFuncSetAttribute(k_conv3, cudaFuncAttributeMaxDynamicSharedMemorySize, smem_conv3);
        cudaFuncSetAttribute(k_quant, cudaFuncAttributeMaxDynamicSharedMemorySize, smem_quant);
        cudaFuncSetAttribute(k_lstm,  cudaFuncAttributeMaxDynamicSharedMemorySize, smem_lstm);
    }
    const int smem_conv2 = (16384 + 64 * 67 + 64) * 4;
    const int smem_conv3 = (12288 + 64 * 34 + 64) * 4;
    const int smem_quant = (16384 + 256) * 4;
    const int smem_lstm  = (16 * HH + HH * 33 + 2 * 16 * 32) * 4;

    // tokenizer
    k_mean <<<(BB * TT) / 256, 256>>>(x);
    k_conv1<<<dim3(8, BB), 256>>>(cw1, cb1);
    k_conv2<<<dim3(32, BB), 256, smem_conv2>>>(cw2, cb2);
    k_conv3<<<dim3(32, BB), 256, smem_conv3>>>(cw3, cb3);
    k_quant<<<(BB * TP) / 128, 128, smem_quant>>>(cbook);

    // layer 0: xg = z @ wih0^T + bl0 ; recurrence
    k_gemm<<<dim3(G4 / 64, (BB * TP) / 64), 256>>>(pz, wih0, bl0, pxg, BB * TP, G4, DD);
    k_lstm_init<<<64, 256>>>();
    k_lstm<<<NCTA, 256, smem_lstm>>>(pxg, whh0, ph0);

    // layer 1
    k_gemm<<<dim3(G4 / 64, (BB * TP) / 64), 256>>>(ph0, wih1, bl1, pxg, BB * TP, G4, HH);
    k_lstm_init<<<64, 256>>>();
    k_lstm<<<NCTA, 256, smem_lstm>>>(pxg, whh1, ph1s);

    // head
    k_head<<<(BB * TP) / 8, 256>>>(wout, bout, ph1s, out);
}

// round 11
// speedup vs baseline: 1.3351x; 1.3351x over previous
#include <cuda_runtime.h>
#include <math.h>
#include <stdint.h>
#include <stddef.h>

#define BB   32
#define TT   4096
#define TP   1024
#define DD   64
#define HH   512
#define G4   2048
#define OUTD 6
#define NCTA 128

// ---------------- f32x2 helpers ----------------
__device__ __forceinline__ unsigned long long ffma2(unsigned long long a,
                                                    unsigned long long b,
                                                    unsigned long long c) {
    unsigned long long d;
    asm("fma.rn.f32x2 %0, %1, %2, %3;" : "=l"(d) : "l"(a), "l"(b), "l"(c));
    return d;
}
__device__ __forceinline__ unsigned long long pack2(float lo, float hi) {
    unsigned long long r;
    asm("mov.b64 %0, {%1, %2};" : "=l"(r) : "f"(lo), "f"(hi));
    return r;
}
__device__ __forceinline__ float2 unpack2(unsigned long long v) {
    float2 r;
    asm("mov.b64 {%0, %1}, %2;" : "=f"(r.x), "=f"(r.y) : "l"(v));
    return r;
}
__device__ __forceinline__ float fsigmoid(float x) {
    return __fdividef(1.f, 1.f + __expf(-x));
}
__device__ __forceinline__ float ftanh(float x) {
    return 1.f - __fdividef(2.f, __expf(2.f * x) + 1.f);
}

// ---------------- scratch ----------------
static __device__ float d_sig[BB * TT];
static __device__ float d_c1 [BB * 64 * 2048];
static __device__ float d_c2 [BB * 64 * 1024];
static __device__ float d_ze [BB * TP * DD];
static __device__ float d_z  [BB * TP * DD];
static __device__ float d_xg [(size_t)BB * TP * G4];
static __device__ float d_h0 [(size_t)BB * TP * HH];
static __device__ float d_h1s[(size_t)BB * TP * HH];
static __device__ float d_hbuf[2 * HH * BB];     // [buf][b][j]
static __device__ int   d_flags[TP];

// ---------------- tokenizer ----------------
__global__ void k_mean(const float* __restrict__ x) {
    int idx = blockIdx.x * 256 + threadIdx.x;            // b*T + t
    const float4* xp = (const float4*)x + (size_t)idx * 16;
    float s = 0.f;
#pragma unroll
    for (int i = 0; i < 16; i++) { float4 v = xp[i]; s += v.x + v.y + v.z + v.w; }
    d_sig[idx] = s * (1.0f / 64.0f);
}

__global__ void k_conv1(const float* __restrict__ w1, const float* __restrict__ b1) {
    __shared__ float ws[256];
    __shared__ float bs[64];
    int tid = threadIdx.x;
    if (tid < 256) ws[tid] = w1[tid];
    if (tid < 64)  bs[tid] = b1[tid];
    __syncthreads();
    int b = blockIdx.y;
    int p = blockIdx.x * 256 + tid;
    const float* sg = d_sig + (size_t)b * TT;
    float in[4];
#pragma unroll
    for (int j = 0; j < 4; j++) {
        int q = 2 * p + j - 1;
        in[j] = (q >= 0 && q < TT) ? sg[q] : 0.f;
    }
    for (int o = 0; o < 64; o++) {
        float a = bs[o];
#pragma unroll
        for (int j = 0; j < 4; j++) a = fmaf(ws[o * 4 + j], in[j], a);
        d_c1[((size_t)(b * 64 + o)) * 2048 + p] = fmaxf(a, 0.f);
    }
}

__global__ void k_conv2(const float* __restrict__ w2, const float* __restrict__ b2) {
    extern __shared__ float sm2[];
    float* ws    = sm2;                 // 64*64*4
    float* patch = ws + 16384;          // 64*67
    float* bs    = patch + 64 * 67;
    int tid = threadIdx.x;
    for (int i = tid; i < 16384; i += 256) ws[i] = w2[i];
    if (tid < 64) bs[tid] = b2[tid];
    int b  = blockIdx.y;
    int p0 = blockIdx.x * 32;
    int q0 = 2 * p0 - 1;
    for (int i = tid; i < 64 * 67; i += 256) {
        int c = i / 67, dq = i % 67, q = q0 + dq;
        patch[i] = (q >= 0 && q < 2048) ? d_c1[((size_t)(b * 64 + c)) * 2048 + q] : 0.f;
    }
    __syncthreads();
    int po = tid & 31, og = tid >> 5;
    float acc[8];
#pragma unroll
    for (int i = 0; i < 8; i++) acc[i] = 0.f;
    for (int c = 0; c < 64; c++) {
        const float* pc = patch + c * 67 + 2 * po;
        float i0 = pc[0], i1 = pc[1], i2 = pc[2], i3 = pc[3];
#pragma unroll
        for (int oi = 0; oi < 8; oi++) {
            const float* wp = &ws[((og * 8 + oi) * 64 + c) * 4];
            acc[oi] = fmaf(wp[0], i0, fmaf(wp[1], i1, fmaf(wp[2], i2, fmaf(wp[3], i3, acc[oi]))));
        }
    }
#pragma unroll
    for (int oi = 0; oi < 8; oi++) {
        int o = og * 8 + oi;
        d_c2[((size_t)(b * 64 + o)) * 1024 + p0 + po] = fmaxf(acc[oi] + bs[o], 0.f);
    }
}

__global__ void k_conv3(const float* __restrict__ w3, const float* __restrict__ b3) {
    extern __shared__ float sm3[];
    float* ws    = sm3;                 // 64*64*3
    float* patch = ws + 12288;          // 64*34
    float* bs    = patch + 64 * 34;
    int tid = threadIdx.x;
    for (int i = tid; i < 12288; i += 256) ws[i] = w3[i];
    if (tid < 64) bs[tid] = b3[tid];
    int b  = blockIdx.y;
    int p0 = blockIdx.x * 32;
    int q0 = p0 - 1;
    for (int i = tid; i < 64 * 34; i += 256) {
        int c = i / 34, dq = i % 34, q = q0 + dq;
        patch[i] = (q >= 0 && q < 1024) ? d_c2[((size_t)(b * 64 + c)) * 1024 + q] : 0.f;
    }
    __syncthreads();
    int po = tid & 31, og = tid >> 5;
    float acc[8];
#pragma unroll
    for (int i = 0; i < 8; i++) acc[i] = 0.f;
    for (int c = 0; c < 64; c++) {
        const float* pc = patch + c * 34 + po;
        float i0 = pc[0], i1 = pc[1], i2 = pc[2];
#pragma unroll
        for (int oi = 0; oi < 8; oi++) {
            const float* wp = &ws[((og * 8 + oi) * 64 + c) * 3];
            acc[oi] = fmaf(wp[0], i0, fmaf(wp[1], i1, fmaf(wp[2], i2, acc[oi])));
        }
    }
#pragma unroll
    for (int oi = 0; oi < 8; oi++) {
        int d = og * 8 + oi;
        d_ze[((size_t)(b * TP) + p0 + po) * 64 + d] = acc[oi] + bs[d];
    }
}

__global__ void k_quant(const float* __restrict__ cb) {
    extern __shared__ float smq[];
    float* cbs = smq;            // 256*64
    float* cn  = smq + 16384;    // 256
    int tid = threadIdx.x;       // 128 threads
    for (int i = tid; i < 16384; i += 128) cbs[i] = cb[i];
    __syncthreads();
    for (int c = tid; c < 256; c += 128) {
        float s = 0.f;
        const float* cp = cbs + c * 64;
#pragma unroll
        for (int d = 0; d < 64; d++) s = fmaf(cp[d], cp[d], s);
        cn[c] = s;
    }
    __syncthreads();
    int g = blockIdx.x * 128 + tid;
    float4 zr[16];
    const float4* zp = (const float4*)d_ze + (size_t)g * 16;
    float szz = 0.f;
#pragma unroll
    for (int i = 0; i < 16; i++) {
        zr[i] = zp[i];
        szz += zr[i].x * zr[i].x + zr[i].y * zr[i].y + zr[i].z * zr[i].z + zr[i].w * zr[i].w;
    }
    float best = 3.0e38f; int bi = 0;
    for (int c = 0; c < 256; c++) {
        const float4* cp = (const float4*)cbs + c * 16;
        float dot = 0.f;
#pragma unroll
        for (int i = 0; i < 16; i++) {
            float4 w = cp[i];
            dot = fmaf(w.x, zr[i].x, fmaf(w.y, zr[i].y, fmaf(w.z, zr[i].z, fmaf(w.w, zr[i].w, dot))));
        }
        float dist = szz - 2.f * dot + cn[c];
        if (dist < best) { best = dist; bi = c; }
    }
    float4* zo = (float4*)d_z + (size_t)g * 16;
    const float4* cbest = (const float4*)cbs + bi * 16;
#pragma unroll
    for (int i = 0; i < 16; i++) zo[i] = cbest[i];
}

// ---------------- GEMM (f32x2): C[M,N] = A[M,K]*B[N,K]^T + bias[N] ----------------
// 128x128 tile, 256 threads, 16 rows x 4 cols per thread, row-pairs packed in f32x2.
__global__ void __launch_bounds__(256, 2) k_gemm2(
    const float* __restrict__ A, const float* __restrict__ B,
    const float* __restrict__ bias, float* __restrict__ C,
    int M, int N, int K)
{
    __shared__ float As[16][132];
    __shared__ float Bs[16][128];
    int tid = threadIdx.x;
    int bm = blockIdx.y << 7, bn = blockIdx.x << 7;
    int ty = tid >> 5, tx = tid & 31;

    unsigned long long acc[8][4];
#pragma unroll
    for (int p = 0; p < 8; p++)
#pragma unroll
        for (int j = 0; j < 4; j++) acc[p][j] = 0ULL;

    for (int k0 = 0; k0 < K; k0 += 16) {
        __syncthreads();
#pragma unroll
        for (int q = 0; q < 2; q++) {
            int i = tid * 2 + q;
            int r = i >> 2, c4 = (i & 3) << 2;
            float4 av = *(const float4*)(A + (size_t)(bm + r) * K + k0 + c4);
            As[c4 + 0][r] = av.x; As[c4 + 1][r] = av.y;
            As[c4 + 2][r] = av.z; As[c4 + 3][r] = av.w;
            float4 bv = *(const float4*)(B + (size_t)(bn + r) * K + k0 + c4);
            Bs[c4 + 0][r] = bv.x; Bs[c4 + 1][r] = bv.y;
            Bs[c4 + 2][r] = bv.z; Bs[c4 + 3][r] = bv.w;
        }
        __syncthreads();
#pragma unroll 4
        for (int k = 0; k < 16; k++) {
            const ulonglong2* ap = (const ulonglong2*)&As[k][ty << 4];
            ulonglong2 aA = ap[0], aB2 = ap[1], aC = ap[2], aD = ap[3];
            float4 b4 = *(const float4*)&Bs[k][tx << 2];
            unsigned long long d0 = pack2(b4.x, b4.x);
            unsigned long long d1 = pack2(b4.y, b4.y);
            unsigned long long d2 = pack2(b4.z, b4.z);
            unsigned long long d3 = pack2(b4.w, b4.w);
#define ROWF(p, P) \
            acc[p][0] = ffma2(P, d0, acc[p][0]); acc[p][1] = ffma2(P, d1, acc[p][1]); \
            acc[p][2] = ffma2(P, d2, acc[p][2]); acc[p][3] = ffma2(P, d3, acc[p][3]);
            ROWF(0, aA.x)  ROWF(1, aA.y)  ROWF(2, aB2.x) ROWF(3, aB2.y)
            ROWF(4, aC.x)  ROWF(5, aC.y)  ROWF(6, aD.x)  ROWF(7, aD.y)
#undef ROWF
        }
    }
    float b0 = bias[bn + (tx << 2) + 0];
    float b1 = bias[bn + (tx << 2) + 1];
    float b2 = bias[bn + (tx << 2) + 2];
    float b3 = bias[bn + (tx << 2) + 3];
#pragma unroll
    for (int p = 0; p < 8; p++) {
        float2 v0 = unpack2(acc[p][0]);
        float2 v1 = unpack2(acc[p][1]);
        float2 v2 = unpack2(acc[p][2]);
        float2 v3 = unpack2(acc[p][3]);
        int r0 = bm + (ty << 4) + (p << 1);
        float4 o0 = make_float4(v0.x + b0, v1.x + b1, v2.x + b2, v3.x + b3);
        float4 o1 = make_float4(v0.y + b0, v1.y + b1, v2.y + b2, v3.y + b3);
        *(float4*)(C + (size_t)r0 * N + bn + (tx << 2)) = o0;
        *(float4*)(C + (size_t)(r0 + 1) * N + bn + (tx << 2)) = o1;
    }
}

// ---------------- persistent LSTM ----------------
__global__ void k_lstm_init() {
    int i = blockIdx.x * 256 + threadIdx.x;
    if (i < TP) d_flags[i] = 0;
    if (i < HH * BB) d_hbuf[i] = 0.f;
}

// CTA owns 4 hidden units (16 gate rows, packed into 8 f32x2 row-pairs).
// h state [buf][b][j] in global; staged each step into smem hT[b][k] (pad 516).
__global__ void __launch_bounds__(256, 1) k_lstm(
    const float* __restrict__ xg,   // [B,T',4H]
    const float* __restrict__ whh,  // [4H,H]
    float* __restrict__ hseq)       // [B,T',H]
{
    extern __shared__ unsigned long long smx[];
    unsigned long long* whh_p = smx;                 // 8*512 f32x2
    float* hT   = (float*)(smx + 8 * HH);            // 32*516
    float* gbuf = hT + 32 * 516;                     // 4*16*32
    const int tid   = threadIdx.x;
    const int jbase = blockIdx.x * 4;

    // pack whh row pairs: pr = gate*2 + half -> rows (gate*4 + half*2, +1) of this CTA
#pragma unroll
    for (int pr = 0; pr < 8; pr++) {
        int gate = pr >> 1, half = pr & 1;
        const float* w0 = whh + (size_t)(gate * HH + jbase + half * 2) * HH;
        const float* w1 = w0 + HH;
        for (int k = tid; k < HH; k += 256)
            whh_p[pr * HH + k] = pack2(w0[k], w1[k]);
    }

    const int lane = tid & 31, wid = tid >> 5;
    const int prg  = (wid & 1) * 4;     // packed-row group: 0 or 4
    const int kq   = wid >> 1;          // k quarter 0..3
    const int k0   = kq * 128;
    const int gb   = tid >> 2, gu = tid & 3;
    float cst = 0.f;

    for (int t = 0; t < TP; t++) {
        // prefetch xg for this step (hidden under staging + matmul)
        float xv0 = 0.f, xv1 = 0.f, xv2 = 0.f, xv3 = 0.f;
        if (tid < 128) {
            const float* xp = xg + ((size_t)gb * TP + t) * G4 + jbase + gu;
            xv0 = __ldg(xp);        xv1 = __ldg(xp + 512);
            xv2 = __ldg(xp + 1024); xv3 = __ldg(xp + 1536);
        }
        // stage h_t: global [b][j] -> smem hT[b][k] (straight copy, L2-only loads)
        const float4* hg = (const float4*)(d_hbuf + (size_t)(t & 1) * (HH * BB));
#pragma unroll
        for (int it = 0; it < 16; it++) {
            int i = tid + it * 256;
            float4 v = __ldcg(hg + i);
            *(float4*)&hT[(i >> 7) * 516 + ((i & 127) << 2)] = v;
        }
        __syncthreads();
        // matmul: 4 packed row-pairs x 128 k per warp, f32x2
        {
            unsigned long long a0 = 0ULL, a1 = 0ULL, a2 = 0ULL, a3 = 0ULL;
            const float* hp = hT + lane * 516 + k0;
            const unsigned long long* wb = whh_p + k0;
#pragma unroll 2
            for (int kk = 0; kk < 128; kk += 4) {
                float4 hv = *(const float4*)(hp + kk);
                unsigned long long h0 = pack2(hv.x, hv.x);
                unsigned long long h1 = pack2(hv.y, hv.y);
                unsigned long long h2 = pack2(hv.z, hv.z);
                unsigned long long h3 = pack2(hv.w, hv.w);
#define STEPP(p, accv) { \
                const ulonglong2* wp_ = (const ulonglong2*)(wb + (prg + p) * HH + kk); \
                ulonglong2 wa = wp_[0], wc = wp_[1]; \
                accv = ffma2(wa.x, h0, accv); accv = ffma2(wa.y, h1, accv); \
                accv = ffma2(wc.x, h2, accv); accv = ffma2(wc.y, h3, accv); }
                STEPP(0, a0) STEPP(1, a1) STEPP(2, a2) STEPP(3, a3)
#undef STEPP
            }
#define WRB(p, accv) { \
            float2 g = unpack2(accv); \
            int row = (((prg + p) >> 1) << 2) + (((prg + p) & 1) << 1); \
            gbuf[(kq * 16 + row) * 32 + lane]     = g.x; \
            gbuf[(kq * 16 + row + 1) * 32 + lane] = g.y; }
            WRB(0, a0) WRB(1, a1) WRB(2, a2) WRB(3, a3)
#undef WRB
        }
        __syncthreads();
        // gates: 128 threads (b = tid>>2, u = tid&3)
        if (tid < 128) {
            const int b = gb, u = gu, j = jbase + u;
            float gi = xv0, gf = xv1, gg = xv2, go = xv3;
#pragma unroll
            for (int q = 0; q < 4; q++) {
                const float* gp = gbuf + (q * 16 + u) * 32 + b;
                gi += gp[0];
                gf += gp[4 * 32];
                gg += gp[8 * 32];
                go += gp[12 * 32];
            }
            float iv = fsigmoid(gi);
            float fv = fsigmoid(gf);
            float gv = ftanh(gg);
            float ov = fsigmoid(go);
            cst = fmaf(fv, cst, iv * gv);
            float hv = ov * ftanh(cst);
            d_hbuf[(size_t)((t + 1) & 1) * (HH * BB) + b * HH + j] = hv;
            hseq[((size_t)b * TP + t) * HH + j] = hv;
        }
        if (t < TP - 1) {
            __threadfence();
            __syncthreads();
            if (tid == 0) {
                atomicAdd(&d_flags[t], 1);
                while (((volatile int*)d_flags)[t] < NCTA) { }
            }
            __syncthreads();
        }
    }
}

// ---------------- head ----------------
__global__ void k_head(const float* __restrict__ wout, const float* __restrict__ bout,
                       const float* __restrict__ hs, float* __restrict__ out)
{
    __shared__ float ws[OUTD * HH];
    __shared__ float bs[OUTD];
    int tid = threadIdx.x;
    for (int i = tid; i < OUTD * HH; i += 256) ws[i] = wout[i];
    if (tid < OUTD) bs[tid] = bout[tid];
    __syncthreads();
    int warp = tid >> 5, lane = tid & 31;
    int g = blockIdx.x * 8 + warp;       // b*T' + t
    const float4* hp = (const float4*)(hs + (size_t)g * HH);
    float4 hv[4];
#pragma unroll
    for (int c = 0; c < 4; c++) hv[c] = hp[lane + 32 * c];
#pragma unroll
    for (int o = 0; o < OUTD; o++) {
        const float4* wp = (const float4*)(ws + o * HH);
        float s = 0.f;
#pragma unroll
        for (int c = 0; c < 4; c++) {
            float4 w = wp[lane + 32 * c];
            s = fmaf(w.x, hv[c].x, fmaf(w.y, hv[c].y, fmaf(w.z, hv[c].z, fmaf(w.w, hv[c].w, s))));
        }
#pragma unroll
        for (int off = 16; off; off >>= 1) s += __shfl_xor_sync(0xFFFFFFFFu, s, off);
        if (lane == 0) out[(size_t)g * OUTD + o] = s + bs[o];
    }
}

// ---------------- launch ----------------
extern "C" void kernel_launch(void* const* d_in, const int* in_sizes, int n_in,
                              void* d_out, int out_size) {
    (void)in_sizes; (void)n_in; (void)out_size;
    const float* x     = (const float*)d_in[0];
    const float* cw1   = (const float*)d_in[1];
    const float* cb1   = (const float*)d_in[2];
    const float* cw2   = (const float*)d_in[3];
    const float* cb2   = (const float*)d_in[4];
    const float* cw3   = (const float*)d_in[5];
    const float* cb3   = (const float*)d_in[6];
    const float* cbook = (const float*)d_in[7];
    const float* wih0  = (const float*)d_in[8];
    const float* whh0  = (const float*)d_in[9];
    const float* bl0   = (const float*)d_in[10];
    const float* wih1  = (const float*)d_in[11];
    const float* whh1  = (const float*)d_in[12];
    const float* bl1   = (const float*)d_in[13];
    const float* wout  = (const float*)d_in[14];
    const float* bout  = (const float*)d_in[15];
    float* out = (float*)d_out;

    const int smem_conv2 = (16384 + 64 * 67 + 64) * 4;
    const int smem_conv3 = (12288 + 64 * 34 + 64) * 4;
    const int smem_quant = (16384 + 256) * 4;
    const int smem_lstm  = 8 * HH * 8 + 32 * 516 * 4 + 4 * 16 * 32 * 4;  // 107008

    static float *pz = nullptr, *pxg = nullptr, *ph0 = nullptr, *ph1s = nullptr;
    if (!pz) {
        cudaGetSymbolAddress((void**)&pz,   d_z);
        cudaGetSymbolAddress((void**)&pxg,  d_xg);
        cudaGetSymbolAddress((void**)&ph0,  d_h0);
        cudaGetSymbolAddress((void**)&ph1s, d_h1s);
        cudaFuncSetAttribute(k_conv2, cudaFuncAttributeMaxDynamicSharedMemorySize, smem_conv2);
        cudaFuncSetAttribute(k_conv3, cudaFuncAttributeMaxDynamicSharedMemorySize, smem_conv3);
        cudaFuncSetAttribute(k_quant, cudaFuncAttributeMaxDynamicSharedMemorySize, smem_quant);
        cudaFuncSetAttribute(k_lstm,  cudaFuncAttributeMaxDynamicSharedMemorySize, smem_lstm);
    }

    // tokenizer
    k_mean <<<(BB * TT) / 256, 256>>>(x);
    k_conv1<<<dim3(8, BB), 256>>>(cw1, cb1);
    k_conv2<<<dim3(32, BB), 256, smem_conv2>>>(cw2, cb2);
    k_conv3<<<dim3(32, BB), 256, smem_conv3>>>(cw3, cb3);
    k_quant<<<(BB * TP) / 128, 128, smem_quant>>>(cbook);

    // layer 0
    k_gemm2<<<dim3(G4 / 128, (BB * TP) / 128), 256>>>(pz, wih0, bl0, pxg, BB * TP, G4, DD);
    k_lstm_init<<<64, 256>>>();
    k_lstm<<<NCTA, 256, smem_lstm>>>(pxg, whh0, ph0);

    // layer 1
    k_gemm2<<<dim3(G4 / 128, (BB * TP) / 128), 256>>>(ph0, wih1, bl1, pxg, BB * TP, G4, HH);
    k_lstm_init<<<64, 256>>>();
    k_lstm<<<NCTA, 256, smem_lstm>>>(pxg, whh1, ph1s);

    // head
    k_head<<<(BB * TP) / 8, 256>>>(wout, bout, ph1s, out);
}